// round 6
// baseline (speedup 1.0000x reference)
#include <cuda_runtime.h>
#include <cuda_bf16.h>

// LightCSCF: bpr + reg + cscf losses.
// total = e1@e2^T + e1@e1^T = e1 @ (e1+e2)^T -> single 8192x8192x64 GEMM on
// bf16 tensor cores, fused epilogue g(x)=t+max(1,t*C), t=ex2(acc), fused row-sum.
// R6: grid 2048 (wave tail ~1%), warp tile 32x64 (less LDSM duplication),
//     per-warp-half partial planes (no smem rowsum), rowloss+final fully fused
//     into the GEMM via last-CTA counters, prep with 2 rows/warp (MLP 6).

#define BATCH 8192
#define DIM   64
#define NCB   64            // 8192 / 128 column blocks
#define TPC   2             // column tiles per CTA
#define NSTRIPE (NCB / TPC) // 32
#define NPLANE (2 * NCB)    // 128 partial planes (cb x wx)

#define SCALE_A 7.2134752044f      // 5 * log2(e)
#define C_MARG  0.0183156393f      // exp(-margin/T) = exp(-4)

__device__ __nv_bfloat16 g_e1h[BATCH * DIM];
__device__ __nv_bfloat16 g_fh [BATCH * DIM];
__device__ float g_pos[BATCH];
__device__ float g_bpr[BATCH];
__device__ float g_sq [BATCH];
__device__ float g_partial[NPLANE * BATCH];  // [plane][row], plane = cb*2+wx
__device__ float g_blk[NCB * 3];
__device__ unsigned g_cnt_row[NCB];          // per-rowblock completion counters
__device__ unsigned g_ctr = 0;

__device__ __forceinline__ unsigned smem_u32(const void* p) {
    return (unsigned)__cvta_generic_to_shared(p);
}
__device__ __forceinline__ float ex2f(float x) {
    float y; asm("ex2.approx.f32 %0, %1;" : "=f"(y) : "f"(x)); return y;
}
__device__ __forceinline__ void cp16(unsigned dst, const void* src) {
    asm volatile("cp.async.cg.shared.global [%0], [%1], 16;" :: "r"(dst), "l"(src));
}
__device__ __forceinline__ void cp_commit() { asm volatile("cp.async.commit_group;"); }
__device__ __forceinline__ void cp_wait0()  { asm volatile("cp.async.wait_group 0;"); }
__device__ __forceinline__ void cp_wait1()  { asm volatile("cp.async.wait_group 1;"); }

// ---------------------------------------------------------------------------
// Kernel 1: gather + per-row stats + bf16 operand tables. 2 rows per warp.
// ---------------------------------------------------------------------------
__global__ void __launch_bounds__(256) prep_kernel(
    const float* __restrict__ ut, const float* __restrict__ it,
    const int* __restrict__ user, const int* __restrict__ pos,
    const int* __restrict__ neg)
{
    int wid  = threadIdx.x >> 5;
    int lane = threadIdx.x & 31;
    int r0 = blockIdx.x * 16 + wid * 2;
    int r1 = r0 + 1;

    const float2* u0p = (const float2*)(ut + (long long)user[r0] * DIM);
    const float2* u1p = (const float2*)(ut + (long long)user[r1] * DIM);
    const float2* p0p = (const float2*)(it + (long long)pos[r0]  * DIM);
    const float2* p1p = (const float2*)(it + (long long)pos[r1]  * DIM);
    const float2* n0p = (const float2*)(it + (long long)neg[r0]  * DIM);
    const float2* n1p = (const float2*)(it + (long long)neg[r1]  * DIM);
    float2 u0 = u0p[lane], u1 = u1p[lane];
    float2 p0 = p0p[lane], p1 = p1p[lane];
    float2 n0 = n0p[lane], n1 = n1p[lane];

    float up0 = u0.x*p0.x + u0.y*p0.y, up1 = u1.x*p1.x + u1.y*p1.y;
    float un0 = u0.x*n0.x + u0.y*n0.y, un1 = u1.x*n1.x + u1.y*n1.y;
    float uu0 = u0.x*u0.x + u0.y*u0.y, uu1 = u1.x*u1.x + u1.y*u1.y;
    float pp0 = p0.x*p0.x + p0.y*p0.y, pp1 = p1.x*p1.x + p1.y*p1.y;
    float nn0 = n0.x*n0.x + n0.y*n0.y, nn1 = n1.x*n1.x + n1.y*n1.y;

    #pragma unroll
    for (int off = 16; off; off >>= 1) {
        up0 += __shfl_xor_sync(~0u, up0, off); up1 += __shfl_xor_sync(~0u, up1, off);
        un0 += __shfl_xor_sync(~0u, un0, off); un1 += __shfl_xor_sync(~0u, un1, off);
        uu0 += __shfl_xor_sync(~0u, uu0, off); uu1 += __shfl_xor_sync(~0u, uu1, off);
        pp0 += __shfl_xor_sync(~0u, pp0, off); pp1 += __shfl_xor_sync(~0u, pp1, off);
        nn0 += __shfl_xor_sync(~0u, nn0, off); nn1 += __shfl_xor_sync(~0u, nn1, off);
    }

    float inu0 = 1.0f / fmaxf(sqrtf(uu0), 1e-12f);
    float inu1 = 1.0f / fmaxf(sqrtf(uu1), 1e-12f);
    float inp0 = 1.0f / fmaxf(sqrtf(pp0), 1e-12f);
    float inp1 = 1.0f / fmaxf(sqrtf(pp1), 1e-12f);

    float ax0 = u0.x * inu0, ay0 = u0.y * inu0;
    float ax1 = u1.x * inu1, ay1 = u1.y * inu1;
    ((__nv_bfloat162*)(g_e1h + r0 * DIM))[lane] =
        __floats2bfloat162_rn(ax0 * SCALE_A, ay0 * SCALE_A);
    ((__nv_bfloat162*)(g_e1h + r1 * DIM))[lane] =
        __floats2bfloat162_rn(ax1 * SCALE_A, ay1 * SCALE_A);
    ((__nv_bfloat162*)(g_fh + r0 * DIM))[lane] =
        __floats2bfloat162_rn(ax0 + p0.x * inp0, ay0 + p0.y * inp0);
    ((__nv_bfloat162*)(g_fh + r1 * DIM))[lane] =
        __floats2bfloat162_rn(ax1 + p1.x * inp1, ay1 + p1.y * inp1);

    if (lane == 0) {
        float sim0 = up0 * inu0 * inp0, sim1 = up1 * inu1 * inp1;
        float t0 = __expf(sim0 * 5.0f), t1 = __expf(sim1 * 5.0f);
        g_pos[r0] = t0 + fmaxf(1.0f, t0 * C_MARG);
        g_pos[r1] = t1 + fmaxf(1.0f, t1 * C_MARG);
        float x0 = up0 - un0, x1 = up1 - un1;
        g_bpr[r0] = fminf(x0, 0.0f) - log1pf(__expf(-fabsf(x0)));
        g_bpr[r1] = fminf(x1, 0.0f) - log1pf(__expf(-fabsf(x1)));
        g_sq[r0] = uu0 + pp0 + nn0;
        g_sq[r1] = uu1 + pp1 + nn1;
    }
}

// ---------------------------------------------------------------------------
// Kernel 2: tensor GEMM + fused epilogue + row-sum + fused rowloss/final.
// grid (32, 64). CTA: 128-row block, 2 col tiles, A once, B double-buffered.
// 8 warps (4m x 2n), warp tile 32x64. XOR-swizzled pitch-64 smem.
// ---------------------------------------------------------------------------
__global__ void __launch_bounds__(256, 2) gemm_kernel(float* __restrict__ out)
{
    __shared__ __align__(128) __nv_bfloat16 a_s[128 * DIM];       // 16KB
    __shared__ __align__(128) __nv_bfloat16 b_s[2][128 * DIM];    // 32KB

    int tid = threadIdx.x;
    int rby = blockIdx.y;
    int rowBase = rby * 128;
    int cb0 = blockIdx.x * TPC;

    unsigned a_base = smem_u32(a_s);
    unsigned b_base[2] = { smem_u32(b_s[0]), smem_u32(b_s[1]) };

    // Stage A + B0 (group 1), prefetch B1 (group 0), wait for group-1 only.
    {
        const char* ga = (const char*)(g_e1h + rowBase * DIM);
        const char* gb0 = (const char*)(g_fh + (cb0 * 128) * DIM);
        const char* gb1 = (const char*)(g_fh + ((cb0 + 1) * 128) * DIM);
        #pragma unroll
        for (int l = 0; l < 4; l++) {
            int i = tid + l * 256;
            int r = i >> 3, c = i & 7;
            unsigned soff = (unsigned)(r * 128 + ((c ^ (r & 7)) << 4));
            cp16(a_base + soff, ga + r * 128 + c * 16);
            cp16(b_base[0] + soff, gb0 + r * 128 + c * 16);
        }
        cp_commit();
        #pragma unroll
        for (int l = 0; l < 4; l++) {
            int i = tid + l * 256;
            int r = i >> 3, c = i & 7;
            unsigned soff = (unsigned)(r * 128 + ((c ^ (r & 7)) << 4));
            cp16(b_base[1] + soff, gb1 + r * 128 + c * 16);
        }
        cp_commit();
        cp_wait1();
    }
    __syncthreads();

    int wid  = tid >> 5;
    int lane = tid & 31;
    int wy = wid >> 1;        // rows wy*32 .. +31
    int wx = wid & 1;         // cols wx*64 .. +63
    int lr = lane & 15;
    int h  = lane >> 4;
    int x7 = lane & 7;

    #pragma unroll
    for (int t = 0; t < TPC; t++) {
        if (t == 1) { cp_wait0(); __syncthreads(); }
        unsigned b_cur = b_base[t];

        float acc[2][8][4];
        #pragma unroll
        for (int mf = 0; mf < 2; mf++)
            #pragma unroll
            for (int nf = 0; nf < 8; nf++)
                #pragma unroll
                for (int q = 0; q < 4; q++) acc[mf][nf][q] = 0.0f;

        #pragma unroll
        for (int s = 0; s < 4; s++) {
            unsigned sw = (unsigned)(((2 * s + h) ^ x7) << 4);

            unsigned af[2][4];
            #pragma unroll
            for (int mf = 0; mf < 2; mf++)
                asm volatile("ldmatrix.sync.aligned.m8n8.x4.shared.b16 "
                             "{%0,%1,%2,%3}, [%4];"
                             : "=r"(af[mf][0]), "=r"(af[mf][1]),
                               "=r"(af[mf][2]), "=r"(af[mf][3])
                             : "r"(a_base + (wy * 32 + mf * 16 + lr) * 128 + sw));

            #pragma unroll
            for (int g = 0; g < 4; g++) {
                unsigned r0, r1, r2, r3;
                asm volatile("ldmatrix.sync.aligned.m8n8.x4.shared.b16 "
                             "{%0,%1,%2,%3}, [%4];"
                             : "=r"(r0), "=r"(r1), "=r"(r2), "=r"(r3)
                             : "r"(b_cur + (wx * 64 + g * 16 + lr) * 128 + sw));
                #pragma unroll
                for (int mf = 0; mf < 2; mf++) {
                    asm volatile(
                        "mma.sync.aligned.m16n8k16.row.col.f32.bf16.bf16.f32 "
                        "{%0,%1,%2,%3}, {%4,%5,%6,%7}, {%8,%9}, {%0,%1,%2,%3};"
                        : "+f"(acc[mf][2*g][0]), "+f"(acc[mf][2*g][1]),
                          "+f"(acc[mf][2*g][2]), "+f"(acc[mf][2*g][3])
                        : "r"(af[mf][0]), "r"(af[mf][1]),
                          "r"(af[mf][2]), "r"(af[mf][3]), "r"(r0), "r"(r2));
                    asm volatile(
                        "mma.sync.aligned.m16n8k16.row.col.f32.bf16.bf16.f32 "
                        "{%0,%1,%2,%3}, {%4,%5,%6,%7}, {%8,%9}, {%0,%1,%2,%3};"
                        : "+f"(acc[mf][2*g+1][0]), "+f"(acc[mf][2*g+1][1]),
                          "+f"(acc[mf][2*g+1][2]), "+f"(acc[mf][2*g+1][3])
                        : "r"(af[mf][0]), "r"(af[mf][1]),
                          "r"(af[mf][2]), "r"(af[mf][3]), "r"(r1), "r"(r3));
                }
            }
        }

        // Epilogue: t_e = ex2(acc); g = t_e + max(1, t_e*C); partial row-sum.
        int plane = (cb0 + t) * 2 + wx;
        #pragma unroll
        for (int mf = 0; mf < 2; mf++) {
            float rs0 = 0.0f, rs1 = 0.0f;
            #pragma unroll
            for (int nf = 0; nf < 8; nf++) {
                float t0 = ex2f(acc[mf][nf][0]);
                float t1 = ex2f(acc[mf][nf][1]);
                float t2 = ex2f(acc[mf][nf][2]);
                float t3 = ex2f(acc[mf][nf][3]);
                rs0 += t0 + fmaxf(1.0f, t0 * C_MARG);
                rs0 += t1 + fmaxf(1.0f, t1 * C_MARG);
                rs1 += t2 + fmaxf(1.0f, t2 * C_MARG);
                rs1 += t3 + fmaxf(1.0f, t3 * C_MARG);
            }
            #pragma unroll
            for (int off = 1; off <= 2; off <<= 1) {
                rs0 += __shfl_xor_sync(~0u, rs0, off);
                rs1 += __shfl_xor_sync(~0u, rs1, off);
            }
            if ((lane & 3) == 0) {
                int r = rowBase + wy * 32 + mf * 16 + (lane >> 2);
                g_partial[plane * BATCH + r]     = rs0;
                g_partial[plane * BATCH + r + 8] = rs1;
            }
        }
    }

    // ---- Fused rowloss: last CTA of this rowblock reduces the 128 planes ----
    __syncthreads();
    float* scratch = (float*)a_s;      // a_s no longer needed
    unsigned* uflag = (unsigned*)(scratch + 700);
    if (tid == 0) {
        __threadfence();
        unsigned old = atomicAdd(&g_cnt_row[rby], 1u);
        uflag[0] = (old == NSTRIPE - 1);
        if (old == NSTRIPE - 1) g_cnt_row[rby] = 0;   // reset for next replay
    }
    __syncthreads();
    if (!uflag[0]) return;
    __threadfence();

    // 256 threads: row = tid&127, half = tid>>7 sums planes half*64..+63.
    {
        int row = rowBase + (tid & 127);
        int p0 = (tid >> 7) * 64;
        float rs = 0.0f;
        #pragma unroll 8
        for (int p = 0; p < 64; p++)
            rs += g_partial[(p0 + p) * BATCH + row];
        scratch[tid] = rs;
    }
    __syncthreads();

    if (tid < 128) {
        int row = rowBase + tid;
        float rs = scratch[tid] + scratch[tid + 128];   // fixed order
        scratch[256 + tid] = -logf(g_pos[row] / rs + 1e-5f);
        scratch[384 + tid] = g_bpr[row];
        scratch[512 + tid] = g_sq[row];
    }
    __syncthreads();
    #pragma unroll
    for (int s = 64; s; s >>= 1) {
        if (tid < s) {
            scratch[256 + tid] += scratch[256 + tid + s];
            scratch[384 + tid] += scratch[384 + tid + s];
            scratch[512 + tid] += scratch[512 + tid + s];
        }
        __syncthreads();
    }

    if (tid == 0) {
        g_blk[rby * 3 + 0] = scratch[256];
        g_blk[rby * 3 + 1] = scratch[384];
        g_blk[rby * 3 + 2] = scratch[512];
        __threadfence();
        uflag[1] = (atomicAdd(&g_ctr, 1u) == NCB - 1);
    }
    __syncthreads();
    if (!uflag[1]) return;
    __threadfence();

    if (tid < 32) {
        float l = 0.0f, b = 0.0f, s = 0.0f;
        #pragma unroll
        for (int i = tid; i < NCB; i += 32) {   // fixed order -> deterministic
            l += g_blk[i * 3 + 0];
            b += g_blk[i * 3 + 1];
            s += g_blk[i * 3 + 2];
        }
        #pragma unroll
        for (int off = 16; off; off >>= 1) {
            l += __shfl_xor_sync(~0u, l, off);
            b += __shfl_xor_sync(~0u, b, off);
            s += __shfl_xor_sync(~0u, s, off);
        }
        if (tid == 0) {
            out[0] = -b / (float)BATCH;
            out[1] = 1e-4f * 0.5f * s / (float)BATCH;
            out[2] = 0.5f * l / (float)BATCH;
            g_ctr = 0;                           // reset for next replay
        }
    }
}

extern "C" void kernel_launch(void* const* d_in, const int* in_sizes, int n_in,
                              void* d_out, int out_size)
{
    const float* ut  = (const float*)d_in[0];
    const float* it  = (const float*)d_in[1];
    const int* user  = (const int*)d_in[2];
    const int* pos   = (const int*)d_in[3];
    const int* neg   = (const int*)d_in[4];

    prep_kernel<<<BATCH / 16, 256>>>(ut, it, user, pos, neg);
    dim3 grid(NSTRIPE, NCB);
    gemm_kernel<<<grid, 256>>>((float*)d_out);
}

// round 7
// speedup vs baseline: 1.0680x; 1.0680x over previous
#include <cuda_runtime.h>
#include <cuda_bf16.h>

// LightCSCF: bpr + reg + cscf losses.
// total = e1@e2^T + e1@e1^T = e1 @ (e1+e2)^T -> 8192x8192x64 bf16 tensor GEMM,
// fused epilogue g(x)=t+max(1,t*C), t=ex2(acc), fused row-sum.
// R7 (vs R6): occupancy fix. ncu showed occ=23.4% (regs=116 -> 2 CTA/SM) with
// tensor pipe only 28.5% busy => latency-bound. Now: CTA tile 128x64, warp
// tile 16x64 (acc=32 regs), A-frags hoisted & reused across col tiles,
// __launch_bounds__(256,3) -> 3 CTA/SM. Separate rowloss kernel (R5 best).

#define BATCH 8192
#define DIM   64
#define NCB2  128           // 8192 / 64 column blocks
#define TPC   2             // column tiles per CTA
#define NSTRIPE (NCB2 / TPC) // 64 grid.x

#define SCALE_A 7.2134752044f      // 5 * log2(e)
#define C_MARG  0.0183156393f      // exp(-margin/T) = exp(-4)

__device__ __nv_bfloat16 g_e1h[BATCH * DIM];
__device__ __nv_bfloat16 g_fh [BATCH * DIM];
__device__ float g_pos[BATCH];
__device__ float g_bpr[BATCH];
__device__ float g_sq [BATCH];
__device__ float g_partial[NCB2 * BATCH];    // [cb][row]
__device__ float g_blk[64 * 3];
__device__ unsigned g_ctr = 0;

__device__ __forceinline__ unsigned smem_u32(const void* p) {
    return (unsigned)__cvta_generic_to_shared(p);
}
__device__ __forceinline__ float ex2f(float x) {
    float y; asm("ex2.approx.f32 %0, %1;" : "=f"(y) : "f"(x)); return y;
}
__device__ __forceinline__ void cp16(unsigned dst, const void* src) {
    asm volatile("cp.async.cg.shared.global [%0], [%1], 16;" :: "r"(dst), "l"(src));
}
__device__ __forceinline__ void cp_commit() { asm volatile("cp.async.commit_group;"); }
__device__ __forceinline__ void cp_wait0()  { asm volatile("cp.async.wait_group 0;"); }

// ---------------------------------------------------------------------------
// Kernel 1: gather + per-row stats + bf16 operand tables. 2 rows per warp.
// ---------------------------------------------------------------------------
__global__ void __launch_bounds__(256) prep_kernel(
    const float* __restrict__ ut, const float* __restrict__ it,
    const int* __restrict__ user, const int* __restrict__ pos,
    const int* __restrict__ neg)
{
    int wid  = threadIdx.x >> 5;
    int lane = threadIdx.x & 31;
    int r0 = blockIdx.x * 16 + wid * 2;
    int r1 = r0 + 1;

    const float2* u0p = (const float2*)(ut + (long long)user[r0] * DIM);
    const float2* u1p = (const float2*)(ut + (long long)user[r1] * DIM);
    const float2* p0p = (const float2*)(it + (long long)pos[r0]  * DIM);
    const float2* p1p = (const float2*)(it + (long long)pos[r1]  * DIM);
    const float2* n0p = (const float2*)(it + (long long)neg[r0]  * DIM);
    const float2* n1p = (const float2*)(it + (long long)neg[r1]  * DIM);
    float2 u0 = u0p[lane], u1 = u1p[lane];
    float2 p0 = p0p[lane], p1 = p1p[lane];
    float2 n0 = n0p[lane], n1 = n1p[lane];

    float up0 = u0.x*p0.x + u0.y*p0.y, up1 = u1.x*p1.x + u1.y*p1.y;
    float un0 = u0.x*n0.x + u0.y*n0.y, un1 = u1.x*n1.x + u1.y*n1.y;
    float uu0 = u0.x*u0.x + u0.y*u0.y, uu1 = u1.x*u1.x + u1.y*u1.y;
    float pp0 = p0.x*p0.x + p0.y*p0.y, pp1 = p1.x*p1.x + p1.y*p1.y;
    float nn0 = n0.x*n0.x + n0.y*n0.y, nn1 = n1.x*n1.x + n1.y*n1.y;

    #pragma unroll
    for (int off = 16; off; off >>= 1) {
        up0 += __shfl_xor_sync(~0u, up0, off); up1 += __shfl_xor_sync(~0u, up1, off);
        un0 += __shfl_xor_sync(~0u, un0, off); un1 += __shfl_xor_sync(~0u, un1, off);
        uu0 += __shfl_xor_sync(~0u, uu0, off); uu1 += __shfl_xor_sync(~0u, uu1, off);
        pp0 += __shfl_xor_sync(~0u, pp0, off); pp1 += __shfl_xor_sync(~0u, pp1, off);
        nn0 += __shfl_xor_sync(~0u, nn0, off); nn1 += __shfl_xor_sync(~0u, nn1, off);
    }

    float inu0 = 1.0f / fmaxf(sqrtf(uu0), 1e-12f);
    float inu1 = 1.0f / fmaxf(sqrtf(uu1), 1e-12f);
    float inp0 = 1.0f / fmaxf(sqrtf(pp0), 1e-12f);
    float inp1 = 1.0f / fmaxf(sqrtf(pp1), 1e-12f);

    float ax0 = u0.x * inu0, ay0 = u0.y * inu0;
    float ax1 = u1.x * inu1, ay1 = u1.y * inu1;
    ((__nv_bfloat162*)(g_e1h + r0 * DIM))[lane] =
        __floats2bfloat162_rn(ax0 * SCALE_A, ay0 * SCALE_A);
    ((__nv_bfloat162*)(g_e1h + r1 * DIM))[lane] =
        __floats2bfloat162_rn(ax1 * SCALE_A, ay1 * SCALE_A);
    ((__nv_bfloat162*)(g_fh + r0 * DIM))[lane] =
        __floats2bfloat162_rn(ax0 + p0.x * inp0, ay0 + p0.y * inp0);
    ((__nv_bfloat162*)(g_fh + r1 * DIM))[lane] =
        __floats2bfloat162_rn(ax1 + p1.x * inp1, ay1 + p1.y * inp1);

    if (lane == 0) {
        float sim0 = up0 * inu0 * inp0, sim1 = up1 * inu1 * inp1;
        float t0 = __expf(sim0 * 5.0f), t1 = __expf(sim1 * 5.0f);
        g_pos[r0] = t0 + fmaxf(1.0f, t0 * C_MARG);
        g_pos[r1] = t1 + fmaxf(1.0f, t1 * C_MARG);
        float x0 = up0 - un0, x1 = up1 - un1;
        g_bpr[r0] = fminf(x0, 0.0f) - log1pf(__expf(-fabsf(x0)));
        g_bpr[r1] = fminf(x1, 0.0f) - log1pf(__expf(-fabsf(x1)));
        g_sq[r0] = uu0 + pp0 + nn0;
        g_sq[r1] = uu1 + pp1 + nn1;
    }
}

// ---------------------------------------------------------------------------
// Kernel 2: tensor GEMM + fused epilogue + row-sum.
// grid (64, 64). CTA: 128 rows x 2 col-tiles of 64. 8 warps, warp tile 16x64
// (warp owns full row width -> single partial plane per cb). A frags loaded
// ONCE and reused for both tiles. 3 CTAs/SM.
// ---------------------------------------------------------------------------
__global__ void __launch_bounds__(256, 3) gemm_kernel()
{
    __shared__ __align__(128) __nv_bfloat16 a_s[128 * DIM];     // 16KB
    __shared__ __align__(128) __nv_bfloat16 b_s[2][64 * DIM];   // 2 x 8KB

    int tid = threadIdx.x;
    int rowBase = blockIdx.y * 128;
    int cb0 = blockIdx.x * TPC;

    unsigned a_base = smem_u32(a_s);
    unsigned b_base[2] = { smem_u32(b_s[0]), smem_u32(b_s[1]) };

    // Stage A (1024 chunks) + both B tiles (512 chunks each) with cp.async.
    {
        const char* ga  = (const char*)(g_e1h + rowBase * DIM);
        const char* gb0 = (const char*)(g_fh + (cb0 * 64) * DIM);
        const char* gb1 = (const char*)(g_fh + ((cb0 + 1) * 64) * DIM);
        #pragma unroll
        for (int l = 0; l < 4; l++) {
            int i = tid + l * 256;            // 0..1023
            int r = i >> 3, c = i & 7;
            unsigned soff = (unsigned)(r * 128 + ((c ^ (r & 7)) << 4));
            cp16(a_base + soff, ga + r * 128 + c * 16);
        }
        #pragma unroll
        for (int l = 0; l < 2; l++) {
            int i = tid + l * 256;            // 0..511
            int r = i >> 3, c = i & 7;
            unsigned soff = (unsigned)(r * 128 + ((c ^ (r & 7)) << 4));
            cp16(b_base[0] + soff, gb0 + r * 128 + c * 16);
            cp16(b_base[1] + soff, gb1 + r * 128 + c * 16);
        }
        cp_commit();
        cp_wait0();
    }
    __syncthreads();

    int wid  = tid >> 5;        // warp owns rows wid*16 .. +15
    int lane = tid & 31;
    int lr = lane & 15;
    int h  = lane >> 4;
    int x7 = lane & 7;

    // Hoisted A fragments: all 4 k-steps, reused for both column tiles.
    unsigned af[4][4];
    unsigned a_row = a_base + (wid * 16 + lr) * 128;
    #pragma unroll
    for (int s = 0; s < 4; s++) {
        unsigned sw = (unsigned)(((2 * s + h) ^ x7) << 4);
        asm volatile("ldmatrix.sync.aligned.m8n8.x4.shared.b16 "
                     "{%0,%1,%2,%3}, [%4];"
                     : "=r"(af[s][0]), "=r"(af[s][1]),
                       "=r"(af[s][2]), "=r"(af[s][3])
                     : "r"(a_row + sw));
    }

    #pragma unroll
    for (int t = 0; t < TPC; t++) {
        unsigned b_cur = b_base[t];

        float acc[8][4];
        #pragma unroll
        for (int nf = 0; nf < 8; nf++)
            #pragma unroll
            for (int q = 0; q < 4; q++) acc[nf][q] = 0.0f;

        #pragma unroll
        for (int s = 0; s < 4; s++) {
            unsigned sw = (unsigned)(((2 * s + h) ^ x7) << 4);
            #pragma unroll
            for (int g = 0; g < 4; g++) {     // 64 cols = 4 x (16-col ldmatrix)
                unsigned r0, r1, r2, r3;
                asm volatile("ldmatrix.sync.aligned.m8n8.x4.shared.b16 "
                             "{%0,%1,%2,%3}, [%4];"
                             : "=r"(r0), "=r"(r1), "=r"(r2), "=r"(r3)
                             : "r"(b_cur + (g * 16 + lr) * 128 + sw));
                asm volatile(
                    "mma.sync.aligned.m16n8k16.row.col.f32.bf16.bf16.f32 "
                    "{%0,%1,%2,%3}, {%4,%5,%6,%7}, {%8,%9}, {%0,%1,%2,%3};"
                    : "+f"(acc[2*g][0]), "+f"(acc[2*g][1]),
                      "+f"(acc[2*g][2]), "+f"(acc[2*g][3])
                    : "r"(af[s][0]), "r"(af[s][1]),
                      "r"(af[s][2]), "r"(af[s][3]), "r"(r0), "r"(r2));
                asm volatile(
                    "mma.sync.aligned.m16n8k16.row.col.f32.bf16.bf16.f32 "
                    "{%0,%1,%2,%3}, {%4,%5,%6,%7}, {%8,%9}, {%0,%1,%2,%3};"
                    : "+f"(acc[2*g+1][0]), "+f"(acc[2*g+1][1]),
                      "+f"(acc[2*g+1][2]), "+f"(acc[2*g+1][3])
                    : "r"(af[s][0]), "r"(af[s][1]),
                      "r"(af[s][2]), "r"(af[s][3]), "r"(r1), "r"(r3));
            }
        }

        // Epilogue: t_e = ex2(acc); g = t_e + max(1, t_e*C); row-sum over 64 cols.
        float rs0 = 0.0f, rs1 = 0.0f;
        #pragma unroll
        for (int nf = 0; nf < 8; nf++) {
            float t0 = ex2f(acc[nf][0]);
            float t1 = ex2f(acc[nf][1]);
            float t2 = ex2f(acc[nf][2]);
            float t3 = ex2f(acc[nf][3]);
            rs0 += t0 + fmaxf(1.0f, t0 * C_MARG);
            rs0 += t1 + fmaxf(1.0f, t1 * C_MARG);
            rs1 += t2 + fmaxf(1.0f, t2 * C_MARG);
            rs1 += t3 + fmaxf(1.0f, t3 * C_MARG);
        }
        #pragma unroll
        for (int off = 1; off <= 2; off <<= 1) {
            rs0 += __shfl_xor_sync(~0u, rs0, off);
            rs1 += __shfl_xor_sync(~0u, rs1, off);
        }
        if ((lane & 3) == 0) {
            int r = rowBase + wid * 16 + (lane >> 2);
            int cb = cb0 + t;
            g_partial[cb * BATCH + r]     = rs0;
            g_partial[cb * BATCH + r + 8] = rs1;
        }
    }
}

// ---------------------------------------------------------------------------
// Kernel 3: per-row loss + block sums + last-block final reduction.
// ---------------------------------------------------------------------------
__global__ void __launch_bounds__(128) rowloss_final_kernel(float* __restrict__ out)
{
    int tid = threadIdx.x;
    int row = blockIdx.x * 128 + tid;

    float rs = 0.0f;
    #pragma unroll 16
    for (int cb = 0; cb < NCB2; cb++)
        rs += g_partial[cb * BATCH + row];

    float loss = -logf(g_pos[row] / rs + 1e-5f);
    float bpr = g_bpr[row];
    float sq  = g_sq[row];

    __shared__ float sl[128], sb[128], ss[128];
    sl[tid] = loss; sb[tid] = bpr; ss[tid] = sq;
    __syncthreads();
    #pragma unroll
    for (int s = 64; s; s >>= 1) {
        if (tid < s) {
            sl[tid] += sl[tid + s];
            sb[tid] += sb[tid + s];
            ss[tid] += ss[tid + s];
        }
        __syncthreads();
    }

    __shared__ unsigned isLast;
    if (tid == 0) {
        g_blk[blockIdx.x * 3 + 0] = sl[0];
        g_blk[blockIdx.x * 3 + 1] = sb[0];
        g_blk[blockIdx.x * 3 + 2] = ss[0];
        __threadfence();
        isLast = (atomicAdd(&g_ctr, 1u) == (unsigned)(gridDim.x - 1));
    }
    __syncthreads();

    if (isLast) {
        __threadfence();
        if (tid < 32) {
            float l = 0.0f, b = 0.0f, s = 0.0f;
            for (int i = tid; i < 64; i += 32) {    // fixed order
                l += g_blk[i * 3 + 0];
                b += g_blk[i * 3 + 1];
                s += g_blk[i * 3 + 2];
            }
            #pragma unroll
            for (int off = 16; off; off >>= 1) {
                l += __shfl_xor_sync(~0u, l, off);
                b += __shfl_xor_sync(~0u, b, off);
                s += __shfl_xor_sync(~0u, s, off);
            }
            if (tid == 0) {
                out[0] = -b / (float)BATCH;
                out[1] = 1e-4f * 0.5f * s / (float)BATCH;
                out[2] = 0.5f * l / (float)BATCH;
                g_ctr = 0;                          // reset for next replay
            }
        }
    }
}

extern "C" void kernel_launch(void* const* d_in, const int* in_sizes, int n_in,
                              void* d_out, int out_size)
{
    const float* ut  = (const float*)d_in[0];
    const float* it  = (const float*)d_in[1];
    const int* user  = (const int*)d_in[2];
    const int* pos   = (const int*)d_in[3];
    const int* neg   = (const int*)d_in[4];

    prep_kernel<<<BATCH / 16, 256>>>(ut, it, user, pos, neg);
    dim3 grid(NSTRIPE, 64);
    gemm_kernel<<<grid, 256>>>();
    rowloss_final_kernel<<<64, 128>>>((float*)d_out);
}

// round 8
// speedup vs baseline: 1.1546x; 1.0811x over previous
#include <cuda_runtime.h>
#include <cuda_bf16.h>

// LightCSCF: bpr + reg + cscf losses.
// total = e1@e2^T + e1@e1^T = e1 @ (e1+e2)^T -> 8192x8192x64 bf16 tensor GEMM,
// fused epilogue + row-sum. Epilogue identity used here:
//   g(x) = t + max(1, t*C) = t + C*max(e^4, t),  t = ex2(acc)  (C = e^-4)
// so per element: ex2, fmax, 2 adds; the C* fold happens once per row.
// R8 (vs R7): 4 CTA/SM (launch_bounds(256,4), reg diet: A-frags reloaded per
// k-step, leaner epilogue), single combined partial write per CTA (64 planes),
// prep in 128-thread blocks.

#define BATCH 8192
#define DIM   64
#define TPC   2              // column tiles (64 wide) per CTA
#define NSTRIPE 64           // 8192 / (64*TPC) grid.x
#define NPLANE  NSTRIPE      // one combined partial plane per stripe

#define SCALE_A 7.2134752044f      // 5 * log2(e)
#define C_MARG  0.0183156393f      // exp(-4)
#define INV_C   54.598150033f      // exp(+4)

__device__ __nv_bfloat16 g_e1h[BATCH * DIM];
__device__ __nv_bfloat16 g_fh [BATCH * DIM];
__device__ float g_pos[BATCH];
__device__ float g_bpr[BATCH];
__device__ float g_sq [BATCH];
__device__ float g_partial[NPLANE * BATCH];  // [stripe][row]
__device__ float g_blk[64 * 3];
__device__ unsigned g_ctr = 0;

__device__ __forceinline__ unsigned smem_u32(const void* p) {
    return (unsigned)__cvta_generic_to_shared(p);
}
__device__ __forceinline__ float ex2f(float x) {
    float y; asm("ex2.approx.f32 %0, %1;" : "=f"(y) : "f"(x)); return y;
}
__device__ __forceinline__ void cp16(unsigned dst, const void* src) {
    asm volatile("cp.async.cg.shared.global [%0], [%1], 16;" :: "r"(dst), "l"(src));
}
__device__ __forceinline__ void cp_commit() { asm volatile("cp.async.commit_group;"); }
__device__ __forceinline__ void cp_wait0()  { asm volatile("cp.async.wait_group 0;"); }
__device__ __forceinline__ void cp_wait1()  { asm volatile("cp.async.wait_group 1;"); }

// ---------------------------------------------------------------------------
// Kernel 1: gather + per-row stats + bf16 operand tables.
// 128-thread blocks, 2 rows per warp -> 1024 blocks (fills SMs; gather is
// latency-bound, MLP=6 per lane).
// ---------------------------------------------------------------------------
__global__ void __launch_bounds__(128) prep_kernel(
    const float* __restrict__ ut, const float* __restrict__ it,
    const int* __restrict__ user, const int* __restrict__ pos,
    const int* __restrict__ neg)
{
    int wid  = threadIdx.x >> 5;
    int lane = threadIdx.x & 31;
    int r0 = blockIdx.x * 8 + wid * 2;
    int r1 = r0 + 1;

    const float2* u0p = (const float2*)(ut + (long long)user[r0] * DIM);
    const float2* u1p = (const float2*)(ut + (long long)user[r1] * DIM);
    const float2* p0p = (const float2*)(it + (long long)pos[r0]  * DIM);
    const float2* p1p = (const float2*)(it + (long long)pos[r1]  * DIM);
    const float2* n0p = (const float2*)(it + (long long)neg[r0]  * DIM);
    const float2* n1p = (const float2*)(it + (long long)neg[r1]  * DIM);
    float2 u0 = u0p[lane], u1 = u1p[lane];
    float2 p0 = p0p[lane], p1 = p1p[lane];
    float2 n0 = n0p[lane], n1 = n1p[lane];

    float up0 = u0.x*p0.x + u0.y*p0.y, up1 = u1.x*p1.x + u1.y*p1.y;
    float un0 = u0.x*n0.x + u0.y*n0.y, un1 = u1.x*n1.x + u1.y*n1.y;
    float uu0 = u0.x*u0.x + u0.y*u0.y, uu1 = u1.x*u1.x + u1.y*u1.y;
    float pp0 = p0.x*p0.x + p0.y*p0.y, pp1 = p1.x*p1.x + p1.y*p1.y;
    float nn0 = n0.x*n0.x + n0.y*n0.y, nn1 = n1.x*n1.x + n1.y*n1.y;

    #pragma unroll
    for (int off = 16; off; off >>= 1) {
        up0 += __shfl_xor_sync(~0u, up0, off); up1 += __shfl_xor_sync(~0u, up1, off);
        un0 += __shfl_xor_sync(~0u, un0, off); un1 += __shfl_xor_sync(~0u, un1, off);
        uu0 += __shfl_xor_sync(~0u, uu0, off); uu1 += __shfl_xor_sync(~0u, uu1, off);
        pp0 += __shfl_xor_sync(~0u, pp0, off); pp1 += __shfl_xor_sync(~0u, pp1, off);
        nn0 += __shfl_xor_sync(~0u, nn0, off); nn1 += __shfl_xor_sync(~0u, nn1, off);
    }

    float inu0 = 1.0f / fmaxf(sqrtf(uu0), 1e-12f);
    float inu1 = 1.0f / fmaxf(sqrtf(uu1), 1e-12f);
    float inp0 = 1.0f / fmaxf(sqrtf(pp0), 1e-12f);
    float inp1 = 1.0f / fmaxf(sqrtf(pp1), 1e-12f);

    float ax0 = u0.x * inu0, ay0 = u0.y * inu0;
    float ax1 = u1.x * inu1, ay1 = u1.y * inu1;
    ((__nv_bfloat162*)(g_e1h + r0 * DIM))[lane] =
        __floats2bfloat162_rn(ax0 * SCALE_A, ay0 * SCALE_A);
    ((__nv_bfloat162*)(g_e1h + r1 * DIM))[lane] =
        __floats2bfloat162_rn(ax1 * SCALE_A, ay1 * SCALE_A);
    ((__nv_bfloat162*)(g_fh + r0 * DIM))[lane] =
        __floats2bfloat162_rn(ax0 + p0.x * inp0, ay0 + p0.y * inp0);
    ((__nv_bfloat162*)(g_fh + r1 * DIM))[lane] =
        __floats2bfloat162_rn(ax1 + p1.x * inp1, ay1 + p1.y * inp1);

    if (lane == 0) {
        float sim0 = up0 * inu0 * inp0, sim1 = up1 * inu1 * inp1;
        float t0 = __expf(sim0 * 5.0f), t1 = __expf(sim1 * 5.0f);
        g_pos[r0] = t0 + fmaxf(1.0f, t0 * C_MARG);
        g_pos[r1] = t1 + fmaxf(1.0f, t1 * C_MARG);
        float x0 = up0 - un0, x1 = up1 - un1;
        g_bpr[r0] = fminf(x0, 0.0f) - log1pf(__expf(-fabsf(x0)));
        g_bpr[r1] = fminf(x1, 0.0f) - log1pf(__expf(-fabsf(x1)));
        g_sq[r0] = uu0 + pp0 + nn0;
        g_sq[r1] = uu1 + pp1 + nn1;
    }
}

// ---------------------------------------------------------------------------
// Kernel 2: tensor GEMM + fused epilogue + row-sum.
// grid (64, 64). CTA: 128 rows x 2 col-tiles of 64. 8 warps, warp tile 16x64.
// A-frags reloaded per k-step (low regs). Row-sum accumulated across both
// tiles -> single partial write per row. 4 CTAs/SM.
// ---------------------------------------------------------------------------
__global__ void __launch_bounds__(256, 4) gemm_kernel()
{
    __shared__ __align__(128) __nv_bfloat16 a_s[128 * DIM];     // 16KB
    __shared__ __align__(128) __nv_bfloat16 b_s[2][64 * DIM];   // 2 x 8KB

    int tid = threadIdx.x;
    int rowBase = blockIdx.y * 128;
    int cb0 = blockIdx.x * TPC;

    unsigned a_base = smem_u32(a_s);
    unsigned b_base[2] = { smem_u32(b_s[0]), smem_u32(b_s[1]) };

    // Stage: group0 = A + B0, group1 = B1; incremental waits below.
    {
        const char* ga  = (const char*)(g_e1h + rowBase * DIM);
        const char* gb0 = (const char*)(g_fh + (cb0 * 64) * DIM);
        const char* gb1 = (const char*)(g_fh + ((cb0 + 1) * 64) * DIM);
        #pragma unroll
        for (int l = 0; l < 4; l++) {
            int i = tid + l * 256;            // 0..1023
            int r = i >> 3, c = i & 7;
            unsigned soff = (unsigned)(r * 128 + ((c ^ (r & 7)) << 4));
            cp16(a_base + soff, ga + r * 128 + c * 16);
        }
        #pragma unroll
        for (int l = 0; l < 2; l++) {
            int i = tid + l * 256;            // 0..511
            int r = i >> 3, c = i & 7;
            unsigned soff = (unsigned)(r * 128 + ((c ^ (r & 7)) << 4));
            cp16(b_base[0] + soff, gb0 + r * 128 + c * 16);
        }
        cp_commit();
        #pragma unroll
        for (int l = 0; l < 2; l++) {
            int i = tid + l * 256;
            int r = i >> 3, c = i & 7;
            unsigned soff = (unsigned)(r * 128 + ((c ^ (r & 7)) << 4));
            cp16(b_base[1] + soff, gb1 + r * 128 + c * 16);
        }
        cp_commit();
        cp_wait1();                            // A + B0 ready
    }
    __syncthreads();

    int wid  = tid >> 5;        // warp owns rows wid*16 .. +15
    int lane = tid & 31;
    int lr = lane & 15;
    int h  = lane >> 4;
    int x7 = lane & 7;

    unsigned a_row = a_base + (wid * 16 + lr) * 128;
    unsigned b_row = (unsigned)(lr * 128);

    float rsum_t0 = 0.0f, rsum_m0 = 0.0f;   // Σt and Σmax(e^4,t) halves
    float rsum_t1 = 0.0f, rsum_m1 = 0.0f;

    #pragma unroll
    for (int t = 0; t < TPC; t++) {
        if (t == 1) { cp_wait0(); __syncthreads(); }
        unsigned b_cur = b_base[t] + b_row;

        float acc[8][4];
        #pragma unroll
        for (int nf = 0; nf < 8; nf++)
            #pragma unroll
            for (int q = 0; q < 4; q++) acc[nf][q] = 0.0f;

        #pragma unroll
        for (int s = 0; s < 4; s++) {
            unsigned sw = (unsigned)(((2 * s + h) ^ x7) << 4);

            unsigned af0, af1, af2, af3;
            asm volatile("ldmatrix.sync.aligned.m8n8.x4.shared.b16 "
                         "{%0,%1,%2,%3}, [%4];"
                         : "=r"(af0), "=r"(af1), "=r"(af2), "=r"(af3)
                         : "r"(a_row + sw));

            #pragma unroll
            for (int g = 0; g < 4; g++) {     // 64 cols = 4 x 16-col ldmatrix
                unsigned r0, r1, r2, r3;
                asm volatile("ldmatrix.sync.aligned.m8n8.x4.shared.b16 "
                             "{%0,%1,%2,%3}, [%4];"
                             : "=r"(r0), "=r"(r1), "=r"(r2), "=r"(r3)
                             : "r"(b_cur + g * (16 * 128) + sw));
                asm volatile(
                    "mma.sync.aligned.m16n8k16.row.col.f32.bf16.bf16.f32 "
                    "{%0,%1,%2,%3}, {%4,%5,%6,%7}, {%8,%9}, {%0,%1,%2,%3};"
                    : "+f"(acc[2*g][0]), "+f"(acc[2*g][1]),
                      "+f"(acc[2*g][2]), "+f"(acc[2*g][3])
                    : "r"(af0), "r"(af1), "r"(af2), "r"(af3), "r"(r0), "r"(r2));
                asm volatile(
                    "mma.sync.aligned.m16n8k16.row.col.f32.bf16.bf16.f32 "
                    "{%0,%1,%2,%3}, {%4,%5,%6,%7}, {%8,%9}, {%0,%1,%2,%3};"
                    : "+f"(acc[2*g+1][0]), "+f"(acc[2*g+1][1]),
                      "+f"(acc[2*g+1][2]), "+f"(acc[2*g+1][3])
                    : "r"(af0), "r"(af1), "r"(af2), "r"(af3), "r"(r1), "r"(r3));
            }
        }

        // Epilogue: t_e = ex2(acc); accumulate Σt and Σmax(e^4, t).
        #pragma unroll
        for (int nf = 0; nf < 8; nf++) {
            float t0 = ex2f(acc[nf][0]);
            float t1 = ex2f(acc[nf][1]);
            float t2 = ex2f(acc[nf][2]);
            float t3 = ex2f(acc[nf][3]);
            rsum_t0 += t0 + t1;
            rsum_m0 += fmaxf(INV_C, t0) + fmaxf(INV_C, t1);
            rsum_t1 += t2 + t3;
            rsum_m1 += fmaxf(INV_C, t2) + fmaxf(INV_C, t3);
        }
    }

    // Fold: row partial = Σt + C * Σmax(e^4, t); reduce across 4 lanes.
    float v0 = fmaf(rsum_m0, C_MARG, rsum_t0);
    float v1 = fmaf(rsum_m1, C_MARG, rsum_t1);
    #pragma unroll
    for (int off = 1; off <= 2; off <<= 1) {
        v0 += __shfl_xor_sync(~0u, v0, off);
        v1 += __shfl_xor_sync(~0u, v1, off);
    }
    if ((lane & 3) == 0) {
        int r = rowBase + wid * 16 + (lane >> 2);
        g_partial[blockIdx.x * BATCH + r]     = v0;
        g_partial[blockIdx.x * BATCH + r + 8] = v1;
    }
}

// ---------------------------------------------------------------------------
// Kernel 3: per-row loss + block sums + last-block final reduction.
// ---------------------------------------------------------------------------
__global__ void __launch_bounds__(128) rowloss_final_kernel(float* __restrict__ out)
{
    int tid = threadIdx.x;
    int row = blockIdx.x * 128 + tid;

    float rs = 0.0f;
    #pragma unroll 16
    for (int p = 0; p < NPLANE; p++)
        rs += g_partial[p * BATCH + row];

    float loss = -logf(g_pos[row] / rs + 1e-5f);
    float bpr = g_bpr[row];
    float sq  = g_sq[row];

    __shared__ float sl[128], sb[128], ss[128];
    sl[tid] = loss; sb[tid] = bpr; ss[tid] = sq;
    __syncthreads();
    #pragma unroll
    for (int s = 64; s; s >>= 1) {
        if (tid < s) {
            sl[tid] += sl[tid + s];
            sb[tid] += sb[tid + s];
            ss[tid] += ss[tid + s];
        }
        __syncthreads();
    }

    __shared__ unsigned isLast;
    if (tid == 0) {
        g_blk[blockIdx.x * 3 + 0] = sl[0];
        g_blk[blockIdx.x * 3 + 1] = sb[0];
        g_blk[blockIdx.x * 3 + 2] = ss[0];
        __threadfence();
        isLast = (atomicAdd(&g_ctr, 1u) == (unsigned)(gridDim.x - 1));
    }
    __syncthreads();

    if (isLast) {
        __threadfence();
        if (tid < 32) {
            float l = 0.0f, b = 0.0f, s = 0.0f;
            for (int i = tid; i < 64; i += 32) {    // fixed order
                l += g_blk[i * 3 + 0];
                b += g_blk[i * 3 + 1];
                s += g_blk[i * 3 + 2];
            }
            #pragma unroll
            for (int off = 16; off; off >>= 1) {
                l += __shfl_xor_sync(~0u, l, off);
                b += __shfl_xor_sync(~0u, b, off);
                s += __shfl_xor_sync(~0u, s, off);
            }
            if (tid == 0) {
                out[0] = -b / (float)BATCH;
                out[1] = 1e-4f * 0.5f * s / (float)BATCH;
                out[2] = 0.5f * l / (float)BATCH;
                g_ctr = 0;                          // reset for next replay
            }
        }
    }
}

extern "C" void kernel_launch(void* const* d_in, const int* in_sizes, int n_in,
                              void* d_out, int out_size)
{
    const float* ut  = (const float*)d_in[0];
    const float* it  = (const float*)d_in[1];
    const int* user  = (const int*)d_in[2];
    const int* pos   = (const int*)d_in[3];
    const int* neg   = (const int*)d_in[4];

    prep_kernel<<<BATCH / 8, 128>>>(ut, it, user, pos, neg);
    dim3 grid(NSTRIPE, 64);
    gemm_kernel<<<grid, 256>>>();
    rowloss_final_kernel<<<64, 128>>>((float*)d_out);
}